// round 2
// baseline (speedup 1.0000x reference)
#include <cuda_runtime.h>

#define SEQ 65536
#define HID 1024

// Scratch (allocation-free: __device__ globals)
__device__ float    g_energies[SEQ];
__device__ unsigned g_max_bits;
__device__ double   g_sum;

// Monotonic float<->uint encoding for atomicMax on possibly-negative floats
__device__ __forceinline__ unsigned enc_f(float f) {
    unsigned u = __float_as_uint(f);
    return (u & 0x80000000u) ? ~u : (u | 0x80000000u);
}
__device__ __forceinline__ float dec_u(unsigned e) {
    unsigned u = (e & 0x80000000u) ? (e ^ 0x80000000u) : ~e;
    return __uint_as_float(u);
}

__global__ void init_kernel() {
    g_max_bits = 0u;      // below the encoding of every finite float; safe floor
    g_sum      = 0.0;
}

// One warp per row. 512 threads = 16 warps = 16 rows/block. Grid = SEQ/16 = 4096.
// Each lane: 8 x float4 coalesced loads (512B per warp per access).
__global__ __launch_bounds__(512) void matvec_kernel(
    const float* __restrict__ hidden,
    const float* __restrict__ enc)
{
    __shared__ float sh[HID];
    __shared__ float wmax[16];

    // Stage hidden vector into shared (4 KB) once per block
    for (int i = threadIdx.x; i < HID / 4; i += blockDim.x)
        ((float4*)sh)[i] = ((const float4*)hidden)[i];
    __syncthreads();

    const int warp = threadIdx.x >> 5;
    const int lane = threadIdx.x & 31;
    const int row  = blockIdx.x * 16 + warp;

    const float4* __restrict__ rp = (const float4*)(enc + (size_t)row * HID);
    const float4* __restrict__ hp = (const float4*)sh;

    float acc = 0.f;
#pragma unroll
    for (int k = 0; k < HID / 128; k++) {       // 8 iterations, 8 independent LDG.128
        float4 a = rp[lane + k * 32];
        float4 b = hp[lane + k * 32];
        acc += a.x * b.x + a.y * b.y + a.z * b.z + a.w * b.w;
    }
#pragma unroll
    for (int o = 16; o; o >>= 1)
        acc += __shfl_xor_sync(0xFFFFFFFFu, acc, o);

    if (lane == 0) {
        g_energies[row] = acc;
        wmax[warp] = acc;
    }
    __syncthreads();

    if (threadIdx.x == 0) {
        float m = wmax[0];
#pragma unroll
        for (int i = 1; i < 16; i++) m = fmaxf(m, wmax[i]);
        atomicMax(&g_max_bits, enc_f(m));
    }
}

// Grid-stride sum of exp(e - max) into a double accumulator.
__global__ __launch_bounds__(256) void sumexp_kernel() {
    __shared__ float warp_part[8];
    const float mx = dec_u(g_max_bits);

    float acc = 0.f;
    const float4* ev = (const float4*)g_energies;
    for (int i = blockIdx.x * blockDim.x + threadIdx.x; i < SEQ / 4;
         i += gridDim.x * blockDim.x) {
        float4 e = ev[i];
        acc += expf(e.x - mx) + expf(e.y - mx) + expf(e.z - mx) + expf(e.w - mx);
    }

#pragma unroll
    for (int o = 16; o; o >>= 1)
        acc += __shfl_xor_sync(0xFFFFFFFFu, acc, o);

    const int warp = threadIdx.x >> 5;
    const int lane = threadIdx.x & 31;
    if (lane == 0) warp_part[warp] = acc;
    __syncthreads();

    if (threadIdx.x == 0) {
        float s = 0.f;
#pragma unroll
        for (int i = 0; i < 8; i++) s += warp_part[i];
        atomicAdd(&g_sum, (double)s);
    }
}

__global__ __launch_bounds__(256) void norm_kernel(float4* __restrict__ out) {
    const float mx  = dec_u(g_max_bits);
    const float inv = (float)(1.0 / g_sum);
    const int i = blockIdx.x * blockDim.x + threadIdx.x;   // over SEQ/4 float4s
    float4 e = ((const float4*)g_energies)[i];
    float4 r;
    r.x = expf(e.x - mx) * inv;
    r.y = expf(e.y - mx) * inv;
    r.z = expf(e.z - mx) * inv;
    r.w = expf(e.w - mx) * inv;
    out[i] = r;
}

extern "C" void kernel_launch(void* const* d_in, const int* in_sizes, int n_in,
                              void* d_out, int out_size)
{
    // Disambiguate by element count: hidden has HID elements
    const float* hidden;
    const float* enc;
    if (in_sizes[0] == HID) {
        hidden = (const float*)d_in[0];
        enc    = (const float*)d_in[1];
    } else {
        hidden = (const float*)d_in[1];
        enc    = (const float*)d_in[0];
    }
    float4* out = (float4*)d_out;

    init_kernel<<<1, 1>>>();
    matvec_kernel<<<SEQ / 16, 512>>>(hidden, enc);
    sumexp_kernel<<<128, 256>>>();
    norm_kernel<<<SEQ / 4 / 256, 256>>>(out);
}